// round 13
// baseline (speedup 1.0000x reference)
#include <cuda_runtime.h>
#include <cuda_bf16.h>
#include <cuda_fp16.h>
#include <cstdint>

#define Bn 8
#define Hn 128
#define Wn 128
#define Cn 512
#define NCOL (Bn*Wn)          /* 1024 (b,w) columns */
#define MTOT (Bn*Hn*Wn)       /* 131072 rows */

// x transposed to [B,W,H,C], fp16 hi/lo (exact split of fp32 x)
__device__ __half g_xth[(size_t)NCOL * Hn * Cn];
__device__ __half g_xtl[(size_t)NCOL * Hn * Cn];
// Wv fp16
__device__ __half g_wv16[(size_t)512 * Cn];
// M^T = (Wq^T Wk)^T stored [j][c], fp16 hi/lo
__device__ __half g_mhi[(size_t)512 * 512];
__device__ __half g_mlo[(size_t)512 * 512];
// s = x@M fp16 hi/lo, v fp16; rows [B,W,H]-linear
__device__ __half g_qh[(size_t)NCOL * Hn * Cn];
__device__ __half g_ql[(size_t)NCOL * Hn * Cn];
__device__ __half g_v16[(size_t)NCOL * Hn * Cn];

__device__ __forceinline__ uint32_t smem_u32(const void* p) {
    uint32_t a;
    asm("{ .reg .u64 t; cvta.to.shared.u64 t, %1; cvt.u32.u64 %0, t; }" : "=r"(a) : "l"(p));
    return a;
}
__device__ __forceinline__ void ldsm_x4(uint32_t* r, uint32_t addr) {
    asm volatile("ldmatrix.sync.aligned.m8n8.x4.shared.b16 {%0,%1,%2,%3}, [%4];"
                 : "=r"(r[0]), "=r"(r[1]), "=r"(r[2]), "=r"(r[3]) : "r"(addr));
}
__device__ __forceinline__ void ldsm_x2(uint32_t* r, uint32_t addr) {
    asm volatile("ldmatrix.sync.aligned.m8n8.x2.shared.b16 {%0,%1}, [%2];"
                 : "=r"(r[0]), "=r"(r[1]) : "r"(addr));
}
__device__ __forceinline__ void ldsm_x4_t(uint32_t* r, uint32_t addr) {
    asm volatile("ldmatrix.sync.aligned.m8n8.x4.trans.shared.b16 {%0,%1,%2,%3}, [%4];"
                 : "=r"(r[0]), "=r"(r[1]), "=r"(r[2]), "=r"(r[3]) : "r"(addr));
}
__device__ __forceinline__ void mma_f16(float* c, const uint32_t* a, const uint32_t* b) {
    asm volatile("mma.sync.aligned.m16n8k16.row.col.f32.f16.f16.f32 "
                 "{%0,%1,%2,%3}, {%4,%5,%6,%7}, {%8,%9}, {%0,%1,%2,%3};"
                 : "+f"(c[0]), "+f"(c[1]), "+f"(c[2]), "+f"(c[3])
                 : "r"(a[0]), "r"(a[1]), "r"(a[2]), "r"(a[3]), "r"(b[0]), "r"(b[1]));
}
__device__ __forceinline__ void cp16(uint32_t dst, const void* src) {
    asm volatile("cp.async.cg.shared.global [%0], [%1], 16;"
                 :: "r"(dst), "l"(__cvta_generic_to_global(src)) : "memory");
}
__device__ __forceinline__ uint32_t pack2h(float a, float b) {
    __half2 h = __floats2half2_rn(a, b);
    return *(uint32_t*)&h;
}

// ---------------------------------------------------------------------------
// split_xt: x [B,H,W,C] fp32 -> xth/xtl fp16 hi/lo in [B,W,H,C].
// ---------------------------------------------------------------------------
__global__ __launch_bounds__(128)
void split_xt(const float* __restrict__ x)
{
    const int m = blockIdx.x;
    const int b = m >> 14, h = (m >> 7) & 127, w = m & 127;
    const size_t orow = ((size_t)(b * Wn + w) * Hn + h) * Cn;
    const int c = threadIdx.x * 4;
    float4 v = *(const float4*)(x + (size_t)m * Cn + c);
    float h0 = __half2float(__float2half_rn(v.x));
    float h1 = __half2float(__float2half_rn(v.y));
    float h2 = __half2float(__float2half_rn(v.z));
    float h3 = __half2float(__float2half_rn(v.w));
    uint2 uh, ul;
    uh.x = pack2h(v.x, v.y);           uh.y = pack2h(v.z, v.w);
    ul.x = pack2h(v.x - h0, v.y - h1); ul.y = pack2h(v.z - h2, v.w - h3);
    *(uint2*)(g_xth + orow + c) = uh;
    *(uint2*)(g_xtl + orow + c) = ul;
}

__global__ __launch_bounds__(256)
void split_wv(const float4* __restrict__ Wv)
{
    size_t i = (size_t)blockIdx.x * 256 + threadIdx.x;
    float4 v = Wv[i];
    uint2 uf;
    uf.x = pack2h(v.x, v.y);  uf.y = pack2h(v.z, v.w);
    ((uint2*)g_wv16)[i] = uf;
}

// ---------------------------------------------------------------------------
// wm_mma: M = Wq^T @ Wk (fp32), output Mt[j][c] fp16 hi/lo.
// ---------------------------------------------------------------------------
__global__ __launch_bounds__(256)
void wm_mma(const float* __restrict__ Wq, const float* __restrict__ Wk)
{
    __shared__ float As[16 * 68];
    __shared__ float Bs[16 * 68];
    const int tid = threadIdx.x;
    const int m0 = blockIdx.y * 64;
    const int n0 = blockIdx.x * 64;
    const int tm = (tid >> 4) * 4;
    const int tn = (tid & 15) * 4;
    const int lrow = tid >> 4;
    const int lcol = (tid & 15) * 4;

    float acc[4][4];
#pragma unroll
    for (int i = 0; i < 4; i++)
#pragma unroll
        for (int j = 0; j < 4; j++) acc[i][j] = 0.f;

    for (int r0 = 0; r0 < 512; r0 += 16) {
        *(float4*)&As[lrow * 68 + lcol] = *(const float4*)(Wq + (size_t)(r0 + lrow) * Cn + m0 + lcol);
        *(float4*)&Bs[lrow * 68 + lcol] = *(const float4*)(Wk + (size_t)(r0 + lrow) * Cn + n0 + lcol);
        __syncthreads();
#pragma unroll
        for (int kk = 0; kk < 16; kk++) {
            float4 a4 = *(const float4*)&As[kk * 68 + tm];
            float4 b4 = *(const float4*)&Bs[kk * 68 + tn];
            float a[4] = {a4.x, a4.y, a4.z, a4.w};
            float b[4] = {b4.x, b4.y, b4.z, b4.w};
#pragma unroll
            for (int i = 0; i < 4; i++)
#pragma unroll
                for (int j = 0; j < 4; j++)
                    acc[i][j] = fmaf(a[i], b[j], acc[i][j]);
        }
        __syncthreads();
    }

#pragma unroll
    for (int j = 0; j < 4; j++) {
        const size_t base = (size_t)(n0 + tn + j) * 512 + m0 + tm;
        float e0 = acc[0][j], e1 = acc[1][j], e2 = acc[2][j], e3 = acc[3][j];
        float h0 = __half2float(__float2half_rn(e0));
        float h1 = __half2float(__float2half_rn(e1));
        float h2 = __half2float(__float2half_rn(e2));
        float h3 = __half2float(__float2half_rn(e3));
        *(uint32_t*)(g_mhi + base)     = pack2h(e0, e1);
        *(uint32_t*)(g_mhi + base + 2) = pack2h(e2, e3);
        *(uint32_t*)(g_mlo + base)     = pack2h(e0 - h0, e1 - h1);
        *(uint32_t*)(g_mlo + base + 2) = pack2h(e2 - h2, e3 - h3);
    }
}

// ---------------------------------------------------------------------------
// qkv_fused: R10-proven (CTA 128x128, warp 64x32, K-chunk 32, 2-stage,
// 2 CTAs/SM), xm (even bids, 3-term) + v (odd bids, 1-term) interleaved.
// ---------------------------------------------------------------------------
#define KCH 32
#define NCHUNK (Cn / KCH)         /* 16 */
#define TILE_B 10240              /* 128 rows x 80B */
#define STG_B  (4 * TILE_B)       /* 40960 */

__global__ __launch_bounds__(256, 2)
void qkv_fused()
{
    extern __shared__ char sm[];
    const uint32_t sb = smem_u32(sm);
    const int tid  = threadIdx.x;
    const int wid  = tid >> 5, lane = tid & 31;

    const int bid   = blockIdx.x;           // 0..8191
    const bool three = (bid & 1) == 0;       // even = xm (3-term), odd = v
    const int sub   = bid >> 1;              // 0..4095
    const int n0    = (sub & 3) * 128;
    const int m0    = (sub >> 2) * 128;

    const int warp_m = (wid >> 2) * 64;
    const int warp_n = (wid & 3) * 32;

    const __half* ah_g = g_xth + (size_t)m0 * Cn;
    const __half* al_g = g_xtl + (size_t)m0 * Cn;
    const __half* bh_g = (three ? g_mhi : g_wv16) + (size_t)n0 * Cn;
    const __half* bl_g = g_mlo + (size_t)n0 * Cn;

    auto load_chunk = [&](int s, int k0) {
        const uint32_t stg = sb + s * STG_B;
#pragma unroll
        for (int t = 0; t < 2; t++) {
            const int idx = tid + t * 256;
            const int row = idx >> 2, seg = idx & 3;
            const uint32_t doff = (uint32_t)(row * 80 + seg * 16);
            const size_t goff = (size_t)row * Cn + k0 + seg * 8;
            cp16(stg + doff,              ah_g + goff);
            cp16(stg + 2*TILE_B + doff,   bh_g + goff);
            if (three) {
                cp16(stg + TILE_B + doff,   al_g + goff);
                cp16(stg + 3*TILE_B + doff, bl_g + goff);
            }
        }
        asm volatile("cp.async.commit_group;" ::: "memory");
    };

    float acc[4][4][4];
#pragma unroll
    for (int i = 0; i < 4; i++)
#pragma unroll
        for (int j = 0; j < 4; j++)
#pragma unroll
            for (int q = 0; q < 4; q++) acc[i][j][q] = 0.f;

    const uint32_t a_lane = (uint32_t)((lane & 15) * 80 + (lane >> 4) * 16);
    const uint32_t b_lane = (uint32_t)((lane & 7) * 80 + ((lane >> 3) & 1) * 16);

    load_chunk(0, 0);
    load_chunk(1, KCH);

    for (int k = 0; k < NCHUNK; k++) {
        const int s = k & 1;
        const uint32_t stg = sb + s * STG_B;

        if (k < NCHUNK - 2) asm volatile("cp.async.wait_group 1;" ::: "memory");
        else                asm volatile("cp.async.wait_group 0;" ::: "memory");
        __syncthreads();

        const uint32_t a_hi_base = stg            + warp_m * 80 + a_lane;
        const uint32_t a_lo_base = stg + TILE_B   + warp_m * 80 + a_lane;
        const uint32_t b_hi_base = stg + 2*TILE_B + warp_n * 80 + b_lane;
        const uint32_t b_lo_base = stg + 3*TILE_B + warp_n * 80 + b_lane;

#pragma unroll
        for (int ks = 0; ks < 2; ks++) {
            uint32_t ah[4][4], bh[4][2];
#pragma unroll
            for (int mf = 0; mf < 4; mf++)
                ldsm_x4(ah[mf], a_hi_base + mf * (16 * 80) + ks * 32);
#pragma unroll
            for (int nf = 0; nf < 4; nf++)
                ldsm_x2(bh[nf], b_hi_base + nf * (8 * 80) + ks * 32);
#pragma unroll
            for (int mf = 0; mf < 4; mf++)
#pragma unroll
                for (int nf = 0; nf < 4; nf++)
                    mma_f16(acc[mf][nf], ah[mf], bh[nf]);

            if (three) {
                uint32_t bl[4][2];
#pragma unroll
                for (int nf = 0; nf < 4; nf++)
                    ldsm_x2(bl[nf], b_lo_base + nf * (8 * 80) + ks * 32);
#pragma unroll
                for (int mf = 0; mf < 4; mf++)
#pragma unroll
                    for (int nf = 0; nf < 4; nf++)
                        mma_f16(acc[mf][nf], ah[mf], bl[nf]);

                uint32_t al[4][4];
#pragma unroll
                for (int mf = 0; mf < 4; mf++)
                    ldsm_x4(al[mf], a_lo_base + mf * (16 * 80) + ks * 32);
#pragma unroll
                for (int mf = 0; mf < 4; mf++)
#pragma unroll
                    for (int nf = 0; nf < 4; nf++)
                        mma_f16(acc[mf][nf], al[mf], bh[nf]);
            }
        }
        __syncthreads();

        if (k + 2 < NCHUNK) load_chunk(s, (k + 2) * KCH);
    }

    // epilogue: contiguous [row][col] store; rows are [B,W,H]-linear
    const int col0 = n0 + warp_n;
    const int g   = lane >> 2;
    const int c2i = (lane & 3) * 2;
#pragma unroll
    for (int mf = 0; mf < 4; mf++) {
        const int r = m0 + warp_m + mf * 16 + g;
        const size_t r0 = (size_t)r * Cn + col0 + c2i;
        const size_t r1 = (size_t)(r + 8) * Cn + col0 + c2i;
#pragma unroll
        for (int nf = 0; nf < 4; nf++) {
            float e0 = acc[mf][nf][0], e1 = acc[mf][nf][1];
            float e2 = acc[mf][nf][2], e3 = acc[mf][nf][3];
            if (three) {
                float h0 = __half2float(__float2half_rn(e0));
                float h1 = __half2float(__float2half_rn(e1));
                float h2 = __half2float(__float2half_rn(e2));
                float h3 = __half2float(__float2half_rn(e3));
                *(uint32_t*)(g_qh + r0 + nf * 8) = pack2h(e0, e1);
                *(uint32_t*)(g_ql + r0 + nf * 8) = pack2h(e0 - h0, e1 - h1);
                *(uint32_t*)(g_qh + r1 + nf * 8) = pack2h(e2, e3);
                *(uint32_t*)(g_ql + r1 + nf * 8) = pack2h(e2 - h2, e3 - h3);
            } else {
                *(uint32_t*)(g_v16 + r0 + nf * 8) = pack2h(e0, e1);
                *(uint32_t*)(g_v16 + r1 + nf * 8) = pack2h(e2, e3);
            }
        }
    }
}

// ---------------------------------------------------------------------------
// cc_attn: E = s x^T (3-term fp16), softmax, AV single fp16.
// Phase 2: 32-col chunks, A fragments RELOADED per (chunk, ks) to keep peak
// registers at the phase-1 level (~122) so 2 CTAs/SM are resident.
// ---------------------------------------------------------------------------
#define A_OFF   65536
#define VST_B   10240
#define CC_SMEM 100352

__global__ __launch_bounds__(256, 2)
void cc_attn(const float* __restrict__ x, const float* __restrict__ gamma_p,
             float* __restrict__ out)
{
    extern __shared__ char sm[];
    const uint32_t sb = smem_u32(sm);
    float* E = (float*)sm;
    __half* Ahi = (__half*)(sm + A_OFF);

    const int bw  = blockIdx.x;
    const int b   = bw >> 7;
    const int w   = bw & 127;
    const int tid = threadIdx.x;
    const int wid = tid >> 5, lane = tid & 31;

    const size_t colbase = (size_t)bw * (Hn * Cn);
    const __half* qh = g_qh + colbase;
    const __half* ql = g_ql + colbase;
    const __half* kh = g_xth + colbase;
    const __half* kl = g_xtl + colbase;
    const __half* v16 = g_v16 + colbase;

    const int warp_m = (wid >> 2) * 64;
    const int warp_n = (wid & 3) * 32;

    const uint32_t a_lane = (uint32_t)((lane & 15) * 80 + (lane >> 4) * 16);
    const uint32_t b_lane = (uint32_t)((lane & 7) * 80 + ((lane >> 3) & 1) * 16);

    auto load_chunk = [&](int s, int k0) {
        const uint32_t stg = sb + s * STG_B;
#pragma unroll
        for (int t = 0; t < 2; t++) {
            const int idx = tid + t * 256;
            const int row = idx >> 2, seg = idx & 3;
            const uint32_t doff = (uint32_t)(row * 80 + seg * 16);
            const size_t goff = (size_t)row * Cn + k0 + seg * 8;
            cp16(stg + doff,              qh + goff);
            cp16(stg + 2*TILE_B + doff,   kh + goff);
            cp16(stg + TILE_B + doff,     ql + goff);
            cp16(stg + 3*TILE_B + doff,   kl + goff);
        }
        asm volatile("cp.async.commit_group;" ::: "memory");
    };

    // ---------------- Phase 1 (scoped acc) ----------------
    {
        float acc[4][4][4];
#pragma unroll
        for (int i = 0; i < 4; i++)
#pragma unroll
            for (int j = 0; j < 4; j++)
#pragma unroll
                for (int q = 0; q < 4; q++) acc[i][j][q] = 0.f;

        load_chunk(0, 0);
        load_chunk(1, KCH);

        for (int k = 0; k < NCHUNK; k++) {
            const int s = k & 1;
            const uint32_t stg = sb + s * STG_B;

            if (k < NCHUNK - 2) asm volatile("cp.async.wait_group 1;" ::: "memory");
            else                asm volatile("cp.async.wait_group 0;" ::: "memory");
            __syncthreads();

            const uint32_t a_hi_base = stg            + warp_m * 80 + a_lane;
            const uint32_t a_lo_base = stg + TILE_B   + warp_m * 80 + a_lane;
            const uint32_t b_hi_base = stg + 2*TILE_B + warp_n * 80 + b_lane;
            const uint32_t b_lo_base = stg + 3*TILE_B + warp_n * 80 + b_lane;

#pragma unroll
            for (int ks = 0; ks < 2; ks++) {
                uint32_t ah[4][4], bh[4][2];
#pragma unroll
                for (int mf = 0; mf < 4; mf++)
                    ldsm_x4(ah[mf], a_hi_base + mf * (16 * 80) + ks * 32);
#pragma unroll
                for (int nf = 0; nf < 4; nf++)
                    ldsm_x2(bh[nf], b_hi_base + nf * (8 * 80) + ks * 32);
#pragma unroll
                for (int mf = 0; mf < 4; mf++)
#pragma unroll
                    for (int nf = 0; nf < 4; nf++)
                        mma_f16(acc[mf][nf], ah[mf], bh[nf]);

                uint32_t bl[4][2];
#pragma unroll
                for (int nf = 0; nf < 4; nf++)
                    ldsm_x2(bl[nf], b_lo_base + nf * (8 * 80) + ks * 32);
#pragma unroll
                for (int mf = 0; mf < 4; mf++)
#pragma unroll
                    for (int nf = 0; nf < 4; nf++)
                        mma_f16(acc[mf][nf], ah[mf], bl[nf]);

                uint32_t al[4][4];
#pragma unroll
                for (int mf = 0; mf < 4; mf++)
                    ldsm_x4(al[mf], a_lo_base + mf * (16 * 80) + ks * 32);
#pragma unroll
                for (int mf = 0; mf < 4; mf++)
#pragma unroll
                    for (int nf = 0; nf < 4; nf++)
                        mma_f16(acc[mf][nf], al[mf], bh[nf]);
            }
            __syncthreads();

            if (k + 2 < NCHUNK) load_chunk(s, (k + 2) * KCH);
        }

        // write E (fp32) with diagonal = -inf
        const float NEG_INF = __int_as_float(0xff800000);
        const int gr  = lane >> 2;
        const int c2i = (lane & 3) * 2;
#pragma unroll
        for (int mf = 0; mf < 4; mf++) {
            const int h0r = warp_m + mf * 16 + gr;
            const int h1r = h0r + 8;
#pragma unroll
            for (int nf = 0; nf < 4; nf++) {
                const int gg = warp_n + nf * 8 + c2i;
                E[h0r * 128 + gg    ] = (h0r == gg    ) ? NEG_INF : acc[mf][nf][0];
                E[h0r * 128 + gg + 1] = (h0r == gg + 1) ? NEG_INF : acc[mf][nf][1];
                E[h1r * 128 + gg    ] = (h1r == gg    ) ? NEG_INF : acc[mf][nf][2];
                E[h1r * 128 + gg + 1] = (h1r == gg + 1) ? NEG_INF : acc[mf][nf][3];
            }
        }
    }
    __syncthreads();

    // softmax over g; write A fp16 at stride 136
    for (int r = wid; r < 128; r += 8) {
        float* row = E + r * 128;
        float v0 = row[lane], v1 = row[lane + 32], v2 = row[lane + 64], v3 = row[lane + 96];
        float mx = fmaxf(fmaxf(v0, v1), fmaxf(v2, v3));
#pragma unroll
        for (int o = 16; o > 0; o >>= 1) mx = fmaxf(mx, __shfl_xor_sync(0xffffffffu, mx, o));
        v0 = __expf(v0 - mx); v1 = __expf(v1 - mx);
        v2 = __expf(v2 - mx); v3 = __expf(v3 - mx);
        float s = v0 + v1 + v2 + v3;
#pragma unroll
        for (int o = 16; o > 0; o >>= 1) s += __shfl_xor_sync(0xffffffffu, s, o);
        const float inv = 1.f / s;
        Ahi[r * 136 + lane     ] = __float2half_rn(v0 * inv);
        Ahi[r * 136 + lane + 32] = __float2half_rn(v1 * inv);
        Ahi[r * 136 + lane + 64] = __float2half_rn(v2 * inv);
        Ahi[r * 136 + lane + 96] = __float2half_rn(v3 * inv);
    }
    __syncthreads();

    // ---------------- Phase 2: 32-col chunks, A reloaded per ks ----------------
    auto loadV = [&](int s, int ci) {
        const uint32_t stg = sb + s * VST_B;
        const int c0 = ci * 32;
#pragma unroll
        for (int t = 0; t < 2; t++) {
            const int idx = tid + t * 256;
            const int row = idx >> 2, seg = idx & 3;
            const uint32_t doff = (uint32_t)(row * 80 + seg * 16);
            cp16(stg + doff, v16 + (size_t)row * Cn + c0 + seg * 8);
        }
        asm volatile("cp.async.commit_group;" ::: "memory");
    };

    loadV(0, 0);
    loadV(1, 1);

    const int h0 = wid * 16;
    const uint32_t abase = sb + A_OFF +
        (uint32_t)(((h0 + (lane & 15)) * 136 + (lane >> 4) * 8) * 2);

    const float gam = gamma_p[0];
    const uint32_t v_lane = (uint32_t)(((lane & 7) + ((lane >> 3) & 1) * 8) * 80 +
                                       (lane >> 4) * 16);

    for (int ci = 0; ci < 16; ci++) {
        const int s = ci & 1;
        if (ci < 14) asm volatile("cp.async.wait_group 1;" ::: "memory");
        else         asm volatile("cp.async.wait_group 0;" ::: "memory");
        __syncthreads();

        const uint32_t vs = sb + s * VST_B;

        float acc2[4][4];
#pragma unroll
        for (int j = 0; j < 4; j++)
#pragma unroll
            for (int q = 0; q < 4; q++) acc2[j][q] = 0.f;

#pragma unroll
        for (int ks = 0; ks < 8; ks++) {
            uint32_t Aks[4];
            ldsm_x4(Aks, abase + ks * 32);      // reload: keeps peak regs low
            const uint32_t vrow = vs + (uint32_t)(ks * 16 * 80) + v_lane;
            uint32_t bh0[4], bh1[4];
            ldsm_x4_t(bh0, vrow);
            ldsm_x4_t(bh1, vrow + 32);
            mma_f16(acc2[0], Aks, bh0);
            mma_f16(acc2[1], Aks, bh0 + 2);
            mma_f16(acc2[2], Aks, bh1);
            mma_f16(acc2[3], Aks, bh1 + 2);
        }
        __syncthreads();
        if (ci + 2 < 16) loadV(s, ci + 2);

        const int hr = h0 + (lane >> 2);
#pragma unroll
        for (int j = 0; j < 4; j++) {
            const int c = ci * 32 + j * 8 + (lane & 3) * 2;
            const size_t o0 = ((size_t)(b * Hn + hr)     * Wn + w) * Cn + c;
            const size_t o1 = ((size_t)(b * Hn + hr + 8) * Wn + w) * Cn + c;
            float2 x0 = *(const float2*)(x + o0);
            float2 x1 = *(const float2*)(x + o1);
            float2 r0, r1;
            r0.x = fmaf(gam, acc2[j][0], x0.x);
            r0.y = fmaf(gam, acc2[j][1], x0.y);
            r1.x = fmaf(gam, acc2[j][2], x1.x);
            r1.y = fmaf(gam, acc2[j][3], x1.y);
            *(float2*)(out + o0) = r0;
            *(float2*)(out + o1) = r1;
        }
    }
}

// ---------------------------------------------------------------------------
extern "C" void kernel_launch(void* const* d_in, const int* in_sizes, int n_in,
                              void* d_out, int out_size)
{
    const float* x  = (const float*)d_in[0];
    const float* Wq = (const float*)d_in[1];
    const float* Wk = (const float*)d_in[2];
    const float* Wv = (const float*)d_in[3];
    const float* gm = (const float*)d_in[4];
    float* out = (float*)d_out;

    split_wv<<<512 * 512 / 4 / 256, 256>>>((const float4*)Wv);
    wm_mma<<<dim3(8, 8), 256>>>(Wq, Wk);
    split_xt<<<MTOT, 128>>>(x);

    cudaFuncSetAttribute(qkv_fused, cudaFuncAttributeMaxDynamicSharedMemorySize, 2 * STG_B);
    qkv_fused<<<8192, 256, 2 * STG_B>>>();

    cudaFuncSetAttribute(cc_attn, cudaFuncAttributeMaxDynamicSharedMemorySize, CC_SMEM);
    cc_attn<<<NCOL, 256, CC_SMEM>>>(x, gm, out);
}

// round 14
// speedup vs baseline: 1.0288x; 1.0288x over previous
#include <cuda_runtime.h>
#include <cuda_bf16.h>
#include <cuda_fp16.h>
#include <cstdint>

#define Bn 8
#define Hn 128
#define Wn 128
#define Cn 512
#define NCOL (Bn*Wn)          /* 1024 (b,w) columns */
#define MTOT (Bn*Hn*Wn)       /* 131072 rows */

// x transposed to [B,W,H,C], fp16 hi/lo (exact split of fp32 x)
__device__ __half g_xth[(size_t)NCOL * Hn * Cn];
__device__ __half g_xtl[(size_t)NCOL * Hn * Cn];
// Wv fp16
__device__ __half g_wv16[(size_t)512 * Cn];
// M^T = (Wq^T Wk)^T stored [j][c], fp16 hi/lo
__device__ __half g_mhi[(size_t)512 * 512];
__device__ __half g_mlo[(size_t)512 * 512];
// s = x@M fp16 hi/lo, v fp16; rows [B,W,H]-linear
__device__ __half g_qh[(size_t)NCOL * Hn * Cn];
__device__ __half g_ql[(size_t)NCOL * Hn * Cn];
__device__ __half g_v16[(size_t)NCOL * Hn * Cn];

__device__ __forceinline__ uint32_t smem_u32(const void* p) {
    uint32_t a;
    asm("{ .reg .u64 t; cvta.to.shared.u64 t, %1; cvt.u32.u64 %0, t; }" : "=r"(a) : "l"(p));
    return a;
}
__device__ __forceinline__ void ldsm_x4(uint32_t* r, uint32_t addr) {
    asm volatile("ldmatrix.sync.aligned.m8n8.x4.shared.b16 {%0,%1,%2,%3}, [%4];"
                 : "=r"(r[0]), "=r"(r[1]), "=r"(r[2]), "=r"(r[3]) : "r"(addr));
}
__device__ __forceinline__ void ldsm_x4_t(uint32_t* r, uint32_t addr) {
    asm volatile("ldmatrix.sync.aligned.m8n8.x4.trans.shared.b16 {%0,%1,%2,%3}, [%4];"
                 : "=r"(r[0]), "=r"(r[1]), "=r"(r[2]), "=r"(r[3]) : "r"(addr));
}
__device__ __forceinline__ void mma_f16(float* c, const uint32_t* a, const uint32_t* b) {
    asm volatile("mma.sync.aligned.m16n8k16.row.col.f32.f16.f16.f32 "
                 "{%0,%1,%2,%3}, {%4,%5,%6,%7}, {%8,%9}, {%0,%1,%2,%3};"
                 : "+f"(c[0]), "+f"(c[1]), "+f"(c[2]), "+f"(c[3])
                 : "r"(a[0]), "r"(a[1]), "r"(a[2]), "r"(a[3]), "r"(b[0]), "r"(b[1]));
}
__device__ __forceinline__ void cp16(uint32_t dst, const void* src) {
    asm volatile("cp.async.cg.shared.global [%0], [%1], 16;"
                 :: "r"(dst), "l"(__cvta_generic_to_global(src)) : "memory");
}
__device__ __forceinline__ uint32_t pack2h(float a, float b) {
    __half2 h = __floats2half2_rn(a, b);
    return *(uint32_t*)&h;
}

// ---------------------------------------------------------------------------
// split_xt: x [B,H,W,C] fp32 -> xth/xtl fp16 hi/lo in [B,W,H,C].
// ---------------------------------------------------------------------------
__global__ __launch_bounds__(128)
void split_xt(const float* __restrict__ x)
{
    const int m = blockIdx.x;
    const int b = m >> 14, h = (m >> 7) & 127, w = m & 127;
    const size_t orow = ((size_t)(b * Wn + w) * Hn + h) * Cn;
    const int c = threadIdx.x * 4;
    float4 v = *(const float4*)(x + (size_t)m * Cn + c);
    float h0 = __half2float(__float2half_rn(v.x));
    float h1 = __half2float(__float2half_rn(v.y));
    float h2 = __half2float(__float2half_rn(v.z));
    float h3 = __half2float(__float2half_rn(v.w));
    uint2 uh, ul;
    uh.x = pack2h(v.x, v.y);           uh.y = pack2h(v.z, v.w);
    ul.x = pack2h(v.x - h0, v.y - h1); ul.y = pack2h(v.z - h2, v.w - h3);
    *(uint2*)(g_xth + orow + c) = uh;
    *(uint2*)(g_xtl + orow + c) = ul;
}

__global__ __launch_bounds__(256)
void split_wv(const float4* __restrict__ Wv)
{
    size_t i = (size_t)blockIdx.x * 256 + threadIdx.x;
    float4 v = Wv[i];
    uint2 uf;
    uf.x = pack2h(v.x, v.y);  uf.y = pack2h(v.z, v.w);
    ((uint2*)g_wv16)[i] = uf;
}

// ---------------------------------------------------------------------------
// wm_mma: M = Wq^T @ Wk (fp32), output Mt[j][c] fp16 hi/lo.
// ---------------------------------------------------------------------------
__global__ __launch_bounds__(256)
void wm_mma(const float* __restrict__ Wq, const float* __restrict__ Wk)
{
    __shared__ float As[16 * 68];
    __shared__ float Bs[16 * 68];
    const int tid = threadIdx.x;
    const int m0 = blockIdx.y * 64;
    const int n0 = blockIdx.x * 64;
    const int tm = (tid >> 4) * 4;
    const int tn = (tid & 15) * 4;
    const int lrow = tid >> 4;
    const int lcol = (tid & 15) * 4;

    float acc[4][4];
#pragma unroll
    for (int i = 0; i < 4; i++)
#pragma unroll
        for (int j = 0; j < 4; j++) acc[i][j] = 0.f;

    for (int r0 = 0; r0 < 512; r0 += 16) {
        *(float4*)&As[lrow * 68 + lcol] = *(const float4*)(Wq + (size_t)(r0 + lrow) * Cn + m0 + lcol);
        *(float4*)&Bs[lrow * 68 + lcol] = *(const float4*)(Wk + (size_t)(r0 + lrow) * Cn + n0 + lcol);
        __syncthreads();
#pragma unroll
        for (int kk = 0; kk < 16; kk++) {
            float4 a4 = *(const float4*)&As[kk * 68 + tm];
            float4 b4 = *(const float4*)&Bs[kk * 68 + tn];
            float a[4] = {a4.x, a4.y, a4.z, a4.w};
            float b[4] = {b4.x, b4.y, b4.z, b4.w};
#pragma unroll
            for (int i = 0; i < 4; i++)
#pragma unroll
                for (int j = 0; j < 4; j++)
                    acc[i][j] = fmaf(a[i], b[j], acc[i][j]);
        }
        __syncthreads();
    }

#pragma unroll
    for (int j = 0; j < 4; j++) {
        const size_t base = (size_t)(n0 + tn + j) * 512 + m0 + tm;
        float e0 = acc[0][j], e1 = acc[1][j], e2 = acc[2][j], e3 = acc[3][j];
        float h0 = __half2float(__float2half_rn(e0));
        float h1 = __half2float(__float2half_rn(e1));
        float h2 = __half2float(__float2half_rn(e2));
        float h3 = __half2float(__float2half_rn(e3));
        *(uint32_t*)(g_mhi + base)     = pack2h(e0, e1);
        *(uint32_t*)(g_mhi + base + 2) = pack2h(e2, e3);
        *(uint32_t*)(g_mlo + base)     = pack2h(e0 - h0, e1 - h1);
        *(uint32_t*)(g_mlo + base + 2) = pack2h(e2 - h2, e3 - h3);
    }
}

// ---------------------------------------------------------------------------
// qkv_fused: R10-proven shape; B-fragments now loaded with ldsm_x4 over
// nf-pairs (r0,r1 = even nf frag; r2,r3 = odd nf frag) - same registers,
// half the LDSM instructions on the B side.
// ---------------------------------------------------------------------------
#define KCH 32
#define NCHUNK (Cn / KCH)         /* 16 */
#define TILE_B 10240              /* 128 rows x 80B */
#define STG_B  (4 * TILE_B)       /* 40960 */

__global__ __launch_bounds__(256, 2)
void qkv_fused()
{
    extern __shared__ char sm[];
    const uint32_t sb = smem_u32(sm);
    const int tid  = threadIdx.x;
    const int wid  = tid >> 5, lane = tid & 31;

    const int bid   = blockIdx.x;           // 0..8191
    const bool three = (bid & 1) == 0;       // even = xm (3-term), odd = v
    const int sub   = bid >> 1;              // 0..4095
    const int n0    = (sub & 3) * 128;
    const int m0    = (sub >> 2) * 128;

    const int warp_m = (wid >> 2) * 64;
    const int warp_n = (wid & 3) * 32;

    const __half* ah_g = g_xth + (size_t)m0 * Cn;
    const __half* al_g = g_xtl + (size_t)m0 * Cn;
    const __half* bh_g = (three ? g_mhi : g_wv16) + (size_t)n0 * Cn;
    const __half* bl_g = g_mlo + (size_t)n0 * Cn;

    auto load_chunk = [&](int s, int k0) {
        const uint32_t stg = sb + s * STG_B;
#pragma unroll
        for (int t = 0; t < 2; t++) {
            const int idx = tid + t * 256;
            const int row = idx >> 2, seg = idx & 3;
            const uint32_t doff = (uint32_t)(row * 80 + seg * 16);
            const size_t goff = (size_t)row * Cn + k0 + seg * 8;
            cp16(stg + doff,              ah_g + goff);
            cp16(stg + 2*TILE_B + doff,   bh_g + goff);
            if (three) {
                cp16(stg + TILE_B + doff,   al_g + goff);
                cp16(stg + 3*TILE_B + doff, bl_g + goff);
            }
        }
        asm volatile("cp.async.commit_group;" ::: "memory");
    };

    float acc[4][4][4];
#pragma unroll
    for (int i = 0; i < 4; i++)
#pragma unroll
        for (int j = 0; j < 4; j++)
#pragma unroll
            for (int q = 0; q < 4; q++) acc[i][j][q] = 0.f;

    const uint32_t a_lane  = (uint32_t)((lane & 15) * 80 + (lane >> 4) * 16);
    // nf-pair x4 addressing: lanes 0-7 nf_even k0-7 | 8-15 nf_even k8-15 |
    //                        16-23 nf_odd k0-7 | 24-31 nf_odd k8-15
    const uint32_t b_lane4 = (uint32_t)(((lane & 7) + ((lane >> 4) << 3)) * 80 +
                                        ((lane >> 3) & 1) * 16);

    load_chunk(0, 0);
    load_chunk(1, KCH);

    for (int k = 0; k < NCHUNK; k++) {
        const int s = k & 1;
        const uint32_t stg = sb + s * STG_B;

        if (k < NCHUNK - 2) asm volatile("cp.async.wait_group 1;" ::: "memory");
        else                asm volatile("cp.async.wait_group 0;" ::: "memory");
        __syncthreads();

        const uint32_t a_hi_base = stg            + warp_m * 80 + a_lane;
        const uint32_t a_lo_base = stg + TILE_B   + warp_m * 80 + a_lane;
        const uint32_t b_hi_base = stg + 2*TILE_B + warp_n * 80 + b_lane4;
        const uint32_t b_lo_base = stg + 3*TILE_B + warp_n * 80 + b_lane4;

#pragma unroll
        for (int ks = 0; ks < 2; ks++) {
            uint32_t ah[4][4], bh[2][4];
#pragma unroll
            for (int mf = 0; mf < 4; mf++)
                ldsm_x4(ah[mf], a_hi_base + mf * (16 * 80) + ks * 32);
#pragma unroll
            for (int p = 0; p < 2; p++)
                ldsm_x4(bh[p], b_hi_base + p * (16 * 80) + ks * 32);
#pragma unroll
            for (int mf = 0; mf < 4; mf++)
#pragma unroll
                for (int p = 0; p < 2; p++) {
                    mma_f16(acc[mf][p * 2 + 0], ah[mf], &bh[p][0]);
                    mma_f16(acc[mf][p * 2 + 1], ah[mf], &bh[p][2]);
                }

            if (three) {
                uint32_t bl[2][4];
#pragma unroll
                for (int p = 0; p < 2; p++)
                    ldsm_x4(bl[p], b_lo_base + p * (16 * 80) + ks * 32);
#pragma unroll
                for (int mf = 0; mf < 4; mf++)
#pragma unroll
                    for (int p = 0; p < 2; p++) {
                        mma_f16(acc[mf][p * 2 + 0], ah[mf], &bl[p][0]);
                        mma_f16(acc[mf][p * 2 + 1], ah[mf], &bl[p][2]);
                    }

                uint32_t al[4][4];
#pragma unroll
                for (int mf = 0; mf < 4; mf++)
                    ldsm_x4(al[mf], a_lo_base + mf * (16 * 80) + ks * 32);
#pragma unroll
                for (int mf = 0; mf < 4; mf++)
#pragma unroll
                    for (int p = 0; p < 2; p++) {
                        mma_f16(acc[mf][p * 2 + 0], al[mf], &bh[p][0]);
                        mma_f16(acc[mf][p * 2 + 1], al[mf], &bh[p][2]);
                    }
            }
        }
        __syncthreads();

        if (k + 2 < NCHUNK) load_chunk(s, (k + 2) * KCH);
    }

    // epilogue: contiguous [row][col] store; rows are [B,W,H]-linear
    const int col0 = n0 + warp_n;
    const int g   = lane >> 2;
    const int c2i = (lane & 3) * 2;
#pragma unroll
    for (int mf = 0; mf < 4; mf++) {
        const int r = m0 + warp_m + mf * 16 + g;
        const size_t r0 = (size_t)r * Cn + col0 + c2i;
        const size_t r1 = (size_t)(r + 8) * Cn + col0 + c2i;
#pragma unroll
        for (int nf = 0; nf < 4; nf++) {
            float e0 = acc[mf][nf][0], e1 = acc[mf][nf][1];
            float e2 = acc[mf][nf][2], e3 = acc[mf][nf][3];
            if (three) {
                float h0 = __half2float(__float2half_rn(e0));
                float h1 = __half2float(__float2half_rn(e1));
                float h2 = __half2float(__float2half_rn(e2));
                float h3 = __half2float(__float2half_rn(e3));
                *(uint32_t*)(g_qh + r0 + nf * 8) = pack2h(e0, e1);
                *(uint32_t*)(g_ql + r0 + nf * 8) = pack2h(e0 - h0, e1 - h1);
                *(uint32_t*)(g_qh + r1 + nf * 8) = pack2h(e2, e3);
                *(uint32_t*)(g_ql + r1 + nf * 8) = pack2h(e2 - h2, e3 - h3);
            } else {
                *(uint32_t*)(g_v16 + r0 + nf * 8) = pack2h(e0, e1);
                *(uint32_t*)(g_v16 + r1 + nf * 8) = pack2h(e2, e3);
            }
        }
    }
}

// ---------------------------------------------------------------------------
// cc_attn: E = s x^T (3-term fp16, B via nf-pair ldsm_x4), softmax,
// AV single fp16 (R10-exact phase 2).
// ---------------------------------------------------------------------------
#define A_OFF   65536
#define VST_B   10240
#define CC_SMEM 100352

__global__ __launch_bounds__(256, 2)
void cc_attn(const float* __restrict__ x, const float* __restrict__ gamma_p,
             float* __restrict__ out)
{
    extern __shared__ char sm[];
    const uint32_t sb = smem_u32(sm);
    float* E = (float*)sm;
    __half* Ahi = (__half*)(sm + A_OFF);

    const int bw  = blockIdx.x;
    const int b   = bw >> 7;
    const int w   = bw & 127;
    const int tid = threadIdx.x;
    const int wid = tid >> 5, lane = tid & 31;

    const size_t colbase = (size_t)bw * (Hn * Cn);
    const __half* qh = g_qh + colbase;
    const __half* ql = g_ql + colbase;
    const __half* kh = g_xth + colbase;
    const __half* kl = g_xtl + colbase;
    const __half* v16 = g_v16 + colbase;

    const int warp_m = (wid >> 2) * 64;
    const int warp_n = (wid & 3) * 32;

    auto load_chunk = [&](int s, int k0) {
        const uint32_t stg = sb + s * STG_B;
#pragma unroll
        for (int t = 0; t < 2; t++) {
            const int idx = tid + t * 256;
            const int row = idx >> 2, seg = idx & 3;
            const uint32_t doff = (uint32_t)(row * 80 + seg * 16);
            const size_t goff = (size_t)row * Cn + k0 + seg * 8;
            cp16(stg + doff,              qh + goff);
            cp16(stg + 2*TILE_B + doff,   kh + goff);
            cp16(stg + TILE_B + doff,     ql + goff);
            cp16(stg + 3*TILE_B + doff,   kl + goff);
        }
        asm volatile("cp.async.commit_group;" ::: "memory");
    };

    float acc[4][4][4];
#pragma unroll
    for (int i = 0; i < 4; i++)
#pragma unroll
        for (int j = 0; j < 4; j++)
#pragma unroll
            for (int q = 0; q < 4; q++) acc[i][j][q] = 0.f;

    const uint32_t a_lane  = (uint32_t)((lane & 15) * 80 + (lane >> 4) * 16);
    const uint32_t b_lane4 = (uint32_t)(((lane & 7) + ((lane >> 4) << 3)) * 80 +
                                        ((lane >> 3) & 1) * 16);

    load_chunk(0, 0);
    load_chunk(1, KCH);

    for (int k = 0; k < NCHUNK; k++) {
        const int s = k & 1;
        const uint32_t stg = sb + s * STG_B;

        if (k < NCHUNK - 2) asm volatile("cp.async.wait_group 1;" ::: "memory");
        else                asm volatile("cp.async.wait_group 0;" ::: "memory");
        __syncthreads();

        const uint32_t a_hi_base = stg            + warp_m * 80 + a_lane;
        const uint32_t a_lo_base = stg + TILE_B   + warp_m * 80 + a_lane;
        const uint32_t b_hi_base = stg + 2*TILE_B + warp_n * 80 + b_lane4;
        const uint32_t b_lo_base = stg + 3*TILE_B + warp_n * 80 + b_lane4;

#pragma unroll
        for (int ks = 0; ks < 2; ks++) {
            uint32_t ah[4][4], bh[2][4];
#pragma unroll
            for (int mf = 0; mf < 4; mf++)
                ldsm_x4(ah[mf], a_hi_base + mf * (16 * 80) + ks * 32);
#pragma unroll
            for (int p = 0; p < 2; p++)
                ldsm_x4(bh[p], b_hi_base + p * (16 * 80) + ks * 32);
#pragma unroll
            for (int mf = 0; mf < 4; mf++)
#pragma unroll
                for (int p = 0; p < 2; p++) {
                    mma_f16(acc[mf][p * 2 + 0], ah[mf], &bh[p][0]);
                    mma_f16(acc[mf][p * 2 + 1], ah[mf], &bh[p][2]);
                }

            uint32_t bl[2][4];
#pragma unroll
            for (int p = 0; p < 2; p++)
                ldsm_x4(bl[p], b_lo_base + p * (16 * 80) + ks * 32);
#pragma unroll
            for (int mf = 0; mf < 4; mf++)
#pragma unroll
                for (int p = 0; p < 2; p++) {
                    mma_f16(acc[mf][p * 2 + 0], ah[mf], &bl[p][0]);
                    mma_f16(acc[mf][p * 2 + 1], ah[mf], &bl[p][2]);
                }

            uint32_t al[4][4];
#pragma unroll
            for (int mf = 0; mf < 4; mf++)
                ldsm_x4(al[mf], a_lo_base + mf * (16 * 80) + ks * 32);
#pragma unroll
            for (int mf = 0; mf < 4; mf++)
#pragma unroll
                for (int p = 0; p < 2; p++) {
                    mma_f16(acc[mf][p * 2 + 0], al[mf], &bh[p][0]);
                    mma_f16(acc[mf][p * 2 + 1], al[mf], &bh[p][2]);
                }
        }
        __syncthreads();

        if (k + 2 < NCHUNK) load_chunk(s, (k + 2) * KCH);
    }

    const float NEG_INF = __int_as_float(0xff800000);
    {
        const int gr  = lane >> 2;
        const int c2i = (lane & 3) * 2;
#pragma unroll
        for (int mf = 0; mf < 4; mf++) {
            const int h0r = warp_m + mf * 16 + gr;
            const int h1r = h0r + 8;
#pragma unroll
            for (int nf = 0; nf < 4; nf++) {
                const int gg = warp_n + nf * 8 + c2i;
                E[h0r * 128 + gg    ] = (h0r == gg    ) ? NEG_INF : acc[mf][nf][0];
                E[h0r * 128 + gg + 1] = (h0r == gg + 1) ? NEG_INF : acc[mf][nf][1];
                E[h1r * 128 + gg    ] = (h1r == gg    ) ? NEG_INF : acc[mf][nf][2];
                E[h1r * 128 + gg + 1] = (h1r == gg + 1) ? NEG_INF : acc[mf][nf][3];
            }
        }
    }
    __syncthreads();

    for (int r = wid; r < 128; r += 8) {
        float* row = E + r * 128;
        float v0 = row[lane], v1 = row[lane + 32], v2 = row[lane + 64], v3 = row[lane + 96];
        float mx = fmaxf(fmaxf(v0, v1), fmaxf(v2, v3));
#pragma unroll
        for (int o = 16; o > 0; o >>= 1) mx = fmaxf(mx, __shfl_xor_sync(0xffffffffu, mx, o));
        v0 = __expf(v0 - mx); v1 = __expf(v1 - mx);
        v2 = __expf(v2 - mx); v3 = __expf(v3 - mx);
        float s = v0 + v1 + v2 + v3;
#pragma unroll
        for (int o = 16; o > 0; o >>= 1) s += __shfl_xor_sync(0xffffffffu, s, o);
        const float inv = 1.f / s;
        Ahi[r * 136 + lane     ] = __float2half_rn(v0 * inv);
        Ahi[r * 136 + lane + 32] = __float2half_rn(v1 * inv);
        Ahi[r * 136 + lane + 64] = __float2half_rn(v2 * inv);
        Ahi[r * 136 + lane + 96] = __float2half_rn(v3 * inv);
    }
    __syncthreads();

    auto loadV = [&](int s, int ci) {
        const uint32_t stg = sb + s * VST_B;
        const int c0 = ci * 32;
#pragma unroll
        for (int t = 0; t < 2; t++) {
            const int idx = tid + t * 256;
            const int row = idx >> 2, seg = idx & 3;
            const uint32_t doff = (uint32_t)(row * 80 + seg * 16);
            cp16(stg + doff, v16 + (size_t)row * Cn + c0 + seg * 8);
        }
        asm volatile("cp.async.commit_group;" ::: "memory");
    };

    loadV(0, 0);
    loadV(1, 1);

    const int h0 = wid * 16;
    uint32_t Ah[8][4];
    {
        const uint32_t abase = sb + A_OFF +
            (uint32_t)(((h0 + (lane & 15)) * 136 + (lane >> 4) * 8) * 2);
#pragma unroll
        for (int ks = 0; ks < 8; ks++)
            ldsm_x4(Ah[ks], abase + ks * 32);
    }

    const float gam = gamma_p[0];
    const uint32_t v_lane = (uint32_t)(((lane & 7) + ((lane >> 3) & 1) * 8) * 80 +
                                       (lane >> 4) * 16);

    for (int ci = 0; ci < 16; ci++) {
        const int s = ci & 1;
        if (ci < 14) asm volatile("cp.async.wait_group 1;" ::: "memory");
        else         asm volatile("cp.async.wait_group 0;" ::: "memory");
        __syncthreads();

        const uint32_t vs = sb + s * VST_B;

        float acc2[4][4];
#pragma unroll
        for (int j = 0; j < 4; j++)
#pragma unroll
            for (int q = 0; q < 4; q++) acc2[j][q] = 0.f;

#pragma unroll
        for (int ks = 0; ks < 8; ks++) {
            const uint32_t vrow = vs + (uint32_t)(ks * 16 * 80) + v_lane;
            uint32_t bh0[4], bh1[4];
            ldsm_x4_t(bh0, vrow);
            ldsm_x4_t(bh1, vrow + 32);
            mma_f16(acc2[0], Ah[ks], bh0);
            mma_f16(acc2[1], Ah[ks], bh0 + 2);
            mma_f16(acc2[2], Ah[ks], bh1);
            mma_f16(acc2[3], Ah[ks], bh1 + 2);
        }
        __syncthreads();
        if (ci + 2 < 16) loadV(s, ci + 2);

        const int hr = h0 + (lane >> 2);
#pragma unroll
        for (int j = 0; j < 4; j++) {
            const int c = ci * 32 + j * 8 + (lane & 3) * 2;
            const size_t o0 = ((size_t)(b * Hn + hr)     * Wn + w) * Cn + c;
            const size_t o1 = ((size_t)(b * Hn + hr + 8) * Wn + w) * Cn + c;
            float2 x0 = *(const float2*)(x + o0);
            float2 x1 = *(const float2*)(x + o1);
            float2 r0, r1;
            r0.x = fmaf(gam, acc2[j][0], x0.x);
            r0.y = fmaf(gam, acc2[j][1], x0.y);
            r1.x = fmaf(gam, acc2[j][2], x1.x);
            r1.y = fmaf(gam, acc2[j][3], x1.y);
            *(float2*)(out + o0) = r0;
            *(float2*)(out + o1) = r1;
        }
    }
}

// ---------------------------------------------------------------------------
extern "C" void kernel_launch(void* const* d_in, const int* in_sizes, int n_in,
                              void* d_out, int out_size)
{
    const float* x  = (const float*)d_in[0];
    const float* Wq = (const float*)d_in[1];
    const float* Wk = (const float*)d_in[2];
    const float* Wv = (const float*)d_in[3];
    const float* gm = (const float*)d_in[4];
    float* out = (float*)d_out;

    split_wv<<<512 * 512 / 4 / 256, 256>>>((const float4*)Wv);
    wm_mma<<<dim3(8, 8), 256>>>(Wq, Wk);
    split_xt<<<MTOT, 128>>>(x);

    cudaFuncSetAttribute(qkv_fused, cudaFuncAttributeMaxDynamicSharedMemorySize, 2 * STG_B);
    qkv_fused<<<8192, 256, 2 * STG_B>>>();

    cudaFuncSetAttribute(cc_attn, cudaFuncAttributeMaxDynamicSharedMemorySize, CC_SMEM);
    cc_attn<<<NCOL, 256, CC_SMEM>>>(x, gm, out);
}

// round 15
// speedup vs baseline: 1.0395x; 1.0103x over previous
#include <cuda_runtime.h>
#include <cuda_bf16.h>
#include <cuda_fp16.h>
#include <cstdint>

#define Bn 8
#define Hn 128
#define Wn 128
#define Cn 512
#define NCOL (Bn*Wn)          /* 1024 (b,w) columns */
#define MTOT (Bn*Hn*Wn)       /* 131072 rows */

// x transposed to [B,W,H,C], fp16 hi/lo (exact-ish split of fp32 x)
__device__ __half g_xth[(size_t)NCOL * Hn * Cn];
__device__ __half g_xtl[(size_t)NCOL * Hn * Cn];
// Wv fp16
__device__ __half g_wv16[(size_t)512 * Cn];
// M^T = (Wq^T Wk)^T stored [j][c], fp16 hi/lo
__device__ __half g_mhi[(size_t)512 * 512];
__device__ __half g_mlo[(size_t)512 * 512];
// s = x@M fp16 hi/lo, v fp16; rows [B,W,H]-linear
__device__ __half g_qh[(size_t)NCOL * Hn * Cn];
__device__ __half g_ql[(size_t)NCOL * Hn * Cn];
__device__ __half g_v16[(size_t)NCOL * Hn * Cn];

__device__ __forceinline__ uint32_t smem_u32(const void* p) {
    uint32_t a;
    asm("{ .reg .u64 t; cvta.to.shared.u64 t, %1; cvt.u32.u64 %0, t; }" : "=r"(a) : "l"(p));
    return a;
}
__device__ __forceinline__ void ldsm_x4(uint32_t* r, uint32_t addr) {
    asm volatile("ldmatrix.sync.aligned.m8n8.x4.shared.b16 {%0,%1,%2,%3}, [%4];"
                 : "=r"(r[0]), "=r"(r[1]), "=r"(r[2]), "=r"(r[3]) : "r"(addr));
}
__device__ __forceinline__ void ldsm_x4_t(uint32_t* r, uint32_t addr) {
    asm volatile("ldmatrix.sync.aligned.m8n8.x4.trans.shared.b16 {%0,%1,%2,%3}, [%4];"
                 : "=r"(r[0]), "=r"(r[1]), "=r"(r[2]), "=r"(r[3]) : "r"(addr));
}
__device__ __forceinline__ void mma_f16(float* c, const uint32_t* a, const uint32_t* b) {
    asm volatile("mma.sync.aligned.m16n8k16.row.col.f32.f16.f16.f32 "
                 "{%0,%1,%2,%3}, {%4,%5,%6,%7}, {%8,%9}, {%0,%1,%2,%3};"
                 : "+f"(c[0]), "+f"(c[1]), "+f"(c[2]), "+f"(c[3])
                 : "r"(a[0]), "r"(a[1]), "r"(a[2]), "r"(a[3]), "r"(b[0]), "r"(b[1]));
}
__device__ __forceinline__ void cp16(uint32_t dst, const void* src) {
    asm volatile("cp.async.cg.shared.global [%0], [%1], 16;"
                 :: "r"(dst), "l"(__cvta_generic_to_global(src)) : "memory");
}
__device__ __forceinline__ uint32_t pack2h(float a, float b) {
    __half2 h = __floats2half2_rn(a, b);
    return *(uint32_t*)&h;
}

// ---------------------------------------------------------------------------
// split_xt: x [B,H,W,C] fp32 -> xth/xtl fp16 hi/lo in [B,W,H,C].
// Tail blocks (>= MTOT) convert Wv -> fp16 (merged prep).
// ---------------------------------------------------------------------------
__global__ __launch_bounds__(128)
void split_xt(const float* __restrict__ x, const float* __restrict__ Wv)
{
    const int m = blockIdx.x;
    if (m >= MTOT) {
        const size_t i = (size_t)(m - MTOT) * 128 + threadIdx.x; // uint2 over 512*512/4
        float4 v = ((const float4*)Wv)[i];
        uint2 uf;
        uf.x = pack2h(v.x, v.y);  uf.y = pack2h(v.z, v.w);
        ((uint2*)g_wv16)[i] = uf;
        return;
    }
    const int b = m >> 14, h = (m >> 7) & 127, w = m & 127;
    const size_t orow = ((size_t)(b * Wn + w) * Hn + h) * Cn;
    const int c = threadIdx.x * 4;
    float4 v = *(const float4*)(x + (size_t)m * Cn + c);
    float h0 = __half2float(__float2half_rn(v.x));
    float h1 = __half2float(__float2half_rn(v.y));
    float h2 = __half2float(__float2half_rn(v.z));
    float h3 = __half2float(__float2half_rn(v.w));
    uint2 uh, ul;
    uh.x = pack2h(v.x, v.y);           uh.y = pack2h(v.z, v.w);
    ul.x = pack2h(v.x - h0, v.y - h1); ul.y = pack2h(v.z - h2, v.w - h3);
    *(uint2*)(g_xth + orow + c) = uh;
    *(uint2*)(g_xtl + orow + c) = ul;
}

// ---------------------------------------------------------------------------
// wm_mma: M = Wq^T @ Wk (fp32), output Mt[j][c] fp16 hi/lo.
// ---------------------------------------------------------------------------
__global__ __launch_bounds__(256)
void wm_mma(const float* __restrict__ Wq, const float* __restrict__ Wk)
{
    __shared__ float As[16 * 68];
    __shared__ float Bs[16 * 68];
    const int tid = threadIdx.x;
    const int m0 = blockIdx.y * 64;
    const int n0 = blockIdx.x * 64;
    const int tm = (tid >> 4) * 4;
    const int tn = (tid & 15) * 4;
    const int lrow = tid >> 4;
    const int lcol = (tid & 15) * 4;

    float acc[4][4];
#pragma unroll
    for (int i = 0; i < 4; i++)
#pragma unroll
        for (int j = 0; j < 4; j++) acc[i][j] = 0.f;

    for (int r0 = 0; r0 < 512; r0 += 16) {
        *(float4*)&As[lrow * 68 + lcol] = *(const float4*)(Wq + (size_t)(r0 + lrow) * Cn + m0 + lcol);
        *(float4*)&Bs[lrow * 68 + lcol] = *(const float4*)(Wk + (size_t)(r0 + lrow) * Cn + n0 + lcol);
        __syncthreads();
#pragma unroll
        for (int kk = 0; kk < 16; kk++) {
            float4 a4 = *(const float4*)&As[kk * 68 + tm];
            float4 b4 = *(const float4*)&Bs[kk * 68 + tn];
            float a[4] = {a4.x, a4.y, a4.z, a4.w};
            float b[4] = {b4.x, b4.y, b4.z, b4.w};
#pragma unroll
            for (int i = 0; i < 4; i++)
#pragma unroll
                for (int j = 0; j < 4; j++)
                    acc[i][j] = fmaf(a[i], b[j], acc[i][j]);
        }
        __syncthreads();
    }

#pragma unroll
    for (int j = 0; j < 4; j++) {
        const size_t base = (size_t)(n0 + tn + j) * 512 + m0 + tm;
        float e0 = acc[0][j], e1 = acc[1][j], e2 = acc[2][j], e3 = acc[3][j];
        float h0 = __half2float(__float2half_rn(e0));
        float h1 = __half2float(__float2half_rn(e1));
        float h2 = __half2float(__float2half_rn(e2));
        float h3 = __half2float(__float2half_rn(e3));
        *(uint32_t*)(g_mhi + base)     = pack2h(e0, e1);
        *(uint32_t*)(g_mhi + base + 2) = pack2h(e2, e3);
        *(uint32_t*)(g_mlo + base)     = pack2h(e0 - h0, e1 - h1);
        *(uint32_t*)(g_mlo + base + 2) = pack2h(e2 - h2, e3 - h3);
    }
}

// ---------------------------------------------------------------------------
// qkv_fused: xm (even bids, 3-term, 2-stage R14 path) + v (odd bids, 1-term,
// 4-stage single-sync pipeline in the same 80KB). B via nf-pair ldsm_x4.
// ---------------------------------------------------------------------------
#define KCH 32
#define NCHUNK (Cn / KCH)         /* 16 */
#define TILE_B 10240              /* 128 rows x 80B */
#define STG_B  (4 * TILE_B)       /* 40960 */
#define VSTG_B (2 * TILE_B)       /* 20480: v stage = A + B tile */

__global__ __launch_bounds__(256, 2)
void qkv_fused()
{
    extern __shared__ char sm[];
    const uint32_t sb = smem_u32(sm);
    const int tid  = threadIdx.x;
    const int wid  = tid >> 5, lane = tid & 31;

    const int bid   = blockIdx.x;           // 0..8191
    const bool three = (bid & 1) == 0;       // even = xm (3-term), odd = v
    const int sub   = bid >> 1;              // 0..4095
    const int n0    = (sub & 3) * 128;
    const int m0    = (sub >> 2) * 128;

    const int warp_m = (wid >> 2) * 64;
    const int warp_n = (wid & 3) * 32;

    const __half* ah_g = g_xth + (size_t)m0 * Cn;
    const __half* al_g = g_xtl + (size_t)m0 * Cn;
    const __half* bh_g = (three ? g_mhi : g_wv16) + (size_t)n0 * Cn;
    const __half* bl_g = g_mlo + (size_t)n0 * Cn;

    float acc[4][4][4];
#pragma unroll
    for (int i = 0; i < 4; i++)
#pragma unroll
        for (int j = 0; j < 4; j++)
#pragma unroll
            for (int q = 0; q < 4; q++) acc[i][j][q] = 0.f;

    const uint32_t a_lane  = (uint32_t)((lane & 15) * 80 + (lane >> 4) * 16);
    const uint32_t b_lane4 = (uint32_t)(((lane & 7) + ((lane >> 4) << 3)) * 80 +
                                        ((lane >> 3) & 1) * 16);

    if (three) {
        // ---------------- xm: 2-stage, R14-proven ----------------
        auto load_chunk = [&](int s, int k0) {
            const uint32_t stg = sb + s * STG_B;
#pragma unroll
            for (int t = 0; t < 2; t++) {
                const int idx = tid + t * 256;
                const int row = idx >> 2, seg = idx & 3;
                const uint32_t doff = (uint32_t)(row * 80 + seg * 16);
                const size_t goff = (size_t)row * Cn + k0 + seg * 8;
                cp16(stg + doff,              ah_g + goff);
                cp16(stg + 2*TILE_B + doff,   bh_g + goff);
                cp16(stg + TILE_B + doff,     al_g + goff);
                cp16(stg + 3*TILE_B + doff,   bl_g + goff);
            }
            asm volatile("cp.async.commit_group;" ::: "memory");
        };

        load_chunk(0, 0);
        load_chunk(1, KCH);

        for (int k = 0; k < NCHUNK; k++) {
            const int s = k & 1;
            const uint32_t stg = sb + s * STG_B;

            if (k < NCHUNK - 2) asm volatile("cp.async.wait_group 1;" ::: "memory");
            else                asm volatile("cp.async.wait_group 0;" ::: "memory");
            __syncthreads();

            const uint32_t a_hi_base = stg            + warp_m * 80 + a_lane;
            const uint32_t a_lo_base = stg + TILE_B   + warp_m * 80 + a_lane;
            const uint32_t b_hi_base = stg + 2*TILE_B + warp_n * 80 + b_lane4;
            const uint32_t b_lo_base = stg + 3*TILE_B + warp_n * 80 + b_lane4;

#pragma unroll
            for (int ks = 0; ks < 2; ks++) {
                uint32_t ah[4][4], bh[2][4];
#pragma unroll
                for (int mf = 0; mf < 4; mf++)
                    ldsm_x4(ah[mf], a_hi_base + mf * (16 * 80) + ks * 32);
#pragma unroll
                for (int p = 0; p < 2; p++)
                    ldsm_x4(bh[p], b_hi_base + p * (16 * 80) + ks * 32);
#pragma unroll
                for (int mf = 0; mf < 4; mf++)
#pragma unroll
                    for (int p = 0; p < 2; p++) {
                        mma_f16(acc[mf][p * 2 + 0], ah[mf], &bh[p][0]);
                        mma_f16(acc[mf][p * 2 + 1], ah[mf], &bh[p][2]);
                    }

                uint32_t bl[2][4];
#pragma unroll
                for (int p = 0; p < 2; p++)
                    ldsm_x4(bl[p], b_lo_base + p * (16 * 80) + ks * 32);
#pragma unroll
                for (int mf = 0; mf < 4; mf++)
#pragma unroll
                    for (int p = 0; p < 2; p++) {
                        mma_f16(acc[mf][p * 2 + 0], ah[mf], &bl[p][0]);
                        mma_f16(acc[mf][p * 2 + 1], ah[mf], &bl[p][2]);
                    }

                uint32_t al[4][4];
#pragma unroll
                for (int mf = 0; mf < 4; mf++)
                    ldsm_x4(al[mf], a_lo_base + mf * (16 * 80) + ks * 32);
#pragma unroll
                for (int mf = 0; mf < 4; mf++)
#pragma unroll
                    for (int p = 0; p < 2; p++) {
                        mma_f16(acc[mf][p * 2 + 0], al[mf], &bh[p][0]);
                        mma_f16(acc[mf][p * 2 + 1], al[mf], &bh[p][2]);
                    }
            }
            __syncthreads();

            if (k + 2 < NCHUNK) load_chunk(s, (k + 2) * KCH);
        }
    } else {
        // ---------------- v: 4-stage, single sync per chunk ----------------
        auto load_v = [&](int s, int k0) {
            const uint32_t stg = sb + s * VSTG_B;
#pragma unroll
            for (int t = 0; t < 2; t++) {
                const int idx = tid + t * 256;
                const int row = idx >> 2, seg = idx & 3;
                const uint32_t doff = (uint32_t)(row * 80 + seg * 16);
                const size_t goff = (size_t)row * Cn + k0 + seg * 8;
                cp16(stg + doff,          ah_g + goff);
                cp16(stg + TILE_B + doff, bh_g + goff);
            }
            asm volatile("cp.async.commit_group;" ::: "memory");
        };

        load_v(0, 0);
        load_v(1, KCH);
        load_v(2, 2 * KCH);

        for (int k = 0; k < NCHUNK; k++) {
            if (k <= NCHUNK - 3)      asm volatile("cp.async.wait_group 2;" ::: "memory");
            else if (k == NCHUNK - 2) asm volatile("cp.async.wait_group 1;" ::: "memory");
            else                      asm volatile("cp.async.wait_group 0;" ::: "memory");
            __syncthreads();
            if (k + 3 < NCHUNK) load_v((k + 3) & 3, (k + 3) * KCH);

            const uint32_t stg = sb + (k & 3) * VSTG_B;
            const uint32_t a_base = stg          + warp_m * 80 + a_lane;
            const uint32_t b_base = stg + TILE_B + warp_n * 80 + b_lane4;

#pragma unroll
            for (int ks = 0; ks < 2; ks++) {
                uint32_t ah[4][4], bh[2][4];
#pragma unroll
                for (int mf = 0; mf < 4; mf++)
                    ldsm_x4(ah[mf], a_base + mf * (16 * 80) + ks * 32);
#pragma unroll
                for (int p = 0; p < 2; p++)
                    ldsm_x4(bh[p], b_base + p * (16 * 80) + ks * 32);
#pragma unroll
                for (int mf = 0; mf < 4; mf++)
#pragma unroll
                    for (int p = 0; p < 2; p++) {
                        mma_f16(acc[mf][p * 2 + 0], ah[mf], &bh[p][0]);
                        mma_f16(acc[mf][p * 2 + 1], ah[mf], &bh[p][2]);
                    }
            }
        }
    }

    // epilogue: contiguous [row][col] store; rows are [B,W,H]-linear
    const int col0 = n0 + warp_n;
    const int g   = lane >> 2;
    const int c2i = (lane & 3) * 2;
#pragma unroll
    for (int mf = 0; mf < 4; mf++) {
        const int r = m0 + warp_m + mf * 16 + g;
        const size_t r0 = (size_t)r * Cn + col0 + c2i;
        const size_t r1 = (size_t)(r + 8) * Cn + col0 + c2i;
#pragma unroll
        for (int nf = 0; nf < 4; nf++) {
            float e0 = acc[mf][nf][0], e1 = acc[mf][nf][1];
            float e2 = acc[mf][nf][2], e3 = acc[mf][nf][3];
            if (three) {
                float h0 = __half2float(__float2half_rn(e0));
                float h1 = __half2float(__float2half_rn(e1));
                float h2 = __half2float(__float2half_rn(e2));
                float h3 = __half2float(__float2half_rn(e3));
                *(uint32_t*)(g_qh + r0 + nf * 8) = pack2h(e0, e1);
                *(uint32_t*)(g_ql + r0 + nf * 8) = pack2h(e0 - h0, e1 - h1);
                *(uint32_t*)(g_qh + r1 + nf * 8) = pack2h(e2, e3);
                *(uint32_t*)(g_ql + r1 + nf * 8) = pack2h(e2 - h2, e3 - h3);
            } else {
                *(uint32_t*)(g_v16 + r0 + nf * 8) = pack2h(e0, e1);
                *(uint32_t*)(g_v16 + r1 + nf * 8) = pack2h(e2, e3);
            }
        }
    }
}

// ---------------------------------------------------------------------------
// cc_attn: E = s x^T (3-term fp16, B via nf-pair ldsm_x4), softmax,
// AV single fp16 with 4-stage single-sync V pipeline.
// ---------------------------------------------------------------------------
#define A_OFF   65536
#define VST_B   10240
#define CC_SMEM 100352

__global__ __launch_bounds__(256, 2)
void cc_attn(const float* __restrict__ x, const float* __restrict__ gamma_p,
             float* __restrict__ out)
{
    extern __shared__ char sm[];
    const uint32_t sb = smem_u32(sm);
    float* E = (float*)sm;
    __half* Ahi = (__half*)(sm + A_OFF);

    const int bw  = blockIdx.x;
    const int b   = bw >> 7;
    const int w   = bw & 127;
    const int tid = threadIdx.x;
    const int wid = tid >> 5, lane = tid & 31;

    const size_t colbase = (size_t)bw * (Hn * Cn);
    const __half* qh = g_qh + colbase;
    const __half* ql = g_ql + colbase;
    const __half* kh = g_xth + colbase;
    const __half* kl = g_xtl + colbase;
    const __half* v16 = g_v16 + colbase;

    const int warp_m = (wid >> 2) * 64;
    const int warp_n = (wid & 3) * 32;

    const uint32_t a_lane  = (uint32_t)((lane & 15) * 80 + (lane >> 4) * 16);
    const uint32_t b_lane4 = (uint32_t)(((lane & 7) + ((lane >> 4) << 3)) * 80 +
                                        ((lane >> 3) & 1) * 16);

    auto load_chunk = [&](int s, int k0) {
        const uint32_t stg = sb + s * STG_B;
#pragma unroll
        for (int t = 0; t < 2; t++) {
            const int idx = tid + t * 256;
            const int row = idx >> 2, seg = idx & 3;
            const uint32_t doff = (uint32_t)(row * 80 + seg * 16);
            const size_t goff = (size_t)row * Cn + k0 + seg * 8;
            cp16(stg + doff,              qh + goff);
            cp16(stg + 2*TILE_B + doff,   kh + goff);
            cp16(stg + TILE_B + doff,     ql + goff);
            cp16(stg + 3*TILE_B + doff,   kl + goff);
        }
        asm volatile("cp.async.commit_group;" ::: "memory");
    };

    // ---------------- Phase 1 (scoped acc) ----------------
    {
        float acc[4][4][4];
#pragma unroll
        for (int i = 0; i < 4; i++)
#pragma unroll
            for (int j = 0; j < 4; j++)
#pragma unroll
                for (int q = 0; q < 4; q++) acc[i][j][q] = 0.f;

        load_chunk(0, 0);
        load_chunk(1, KCH);

        for (int k = 0; k < NCHUNK; k++) {
            const int s = k & 1;
            const uint32_t stg = sb + s * STG_B;

            if (k < NCHUNK - 2) asm volatile("cp.async.wait_group 1;" ::: "memory");
            else                asm volatile("cp.async.wait_group 0;" ::: "memory");
            __syncthreads();

            const uint32_t a_hi_base = stg            + warp_m * 80 + a_lane;
            const uint32_t a_lo_base = stg + TILE_B   + warp_m * 80 + a_lane;
            const uint32_t b_hi_base = stg + 2*TILE_B + warp_n * 80 + b_lane4;
            const uint32_t b_lo_base = stg + 3*TILE_B + warp_n * 80 + b_lane4;

#pragma unroll
            for (int ks = 0; ks < 2; ks++) {
                uint32_t ah[4][4], bh[2][4];
#pragma unroll
                for (int mf = 0; mf < 4; mf++)
                    ldsm_x4(ah[mf], a_hi_base + mf * (16 * 80) + ks * 32);
#pragma unroll
                for (int p = 0; p < 2; p++)
                    ldsm_x4(bh[p], b_hi_base + p * (16 * 80) + ks * 32);
#pragma unroll
                for (int mf = 0; mf < 4; mf++)
#pragma unroll
                    for (int p = 0; p < 2; p++) {
                        mma_f16(acc[mf][p * 2 + 0], ah[mf], &bh[p][0]);
                        mma_f16(acc[mf][p * 2 + 1], ah[mf], &bh[p][2]);
                    }

                uint32_t bl[2][4];
#pragma unroll
                for (int p = 0; p < 2; p++)
                    ldsm_x4(bl[p], b_lo_base + p * (16 * 80) + ks * 32);
#pragma unroll
                for (int mf = 0; mf < 4; mf++)
#pragma unroll
                    for (int p = 0; p < 2; p++) {
                        mma_f16(acc[mf][p * 2 + 0], ah[mf], &bl[p][0]);
                        mma_f16(acc[mf][p * 2 + 1], ah[mf], &bl[p][2]);
                    }

                uint32_t al[4][4];
#pragma unroll
                for (int mf = 0; mf < 4; mf++)
                    ldsm_x4(al[mf], a_lo_base + mf * (16 * 80) + ks * 32);
#pragma unroll
                for (int mf = 0; mf < 4; mf++)
#pragma unroll
                    for (int p = 0; p < 2; p++) {
                        mma_f16(acc[mf][p * 2 + 0], al[mf], &bh[p][0]);
                        mma_f16(acc[mf][p * 2 + 1], al[mf], &bh[p][2]);
                    }
            }
            __syncthreads();

            if (k + 2 < NCHUNK) load_chunk(s, (k + 2) * KCH);
        }

        const float NEG_INF = __int_as_float(0xff800000);
        const int gr  = lane >> 2;
        const int c2i = (lane & 3) * 2;
#pragma unroll
        for (int mf = 0; mf < 4; mf++) {
            const int h0r = warp_m + mf * 16 + gr;
            const int h1r = h0r + 8;
#pragma unroll
            for (int nf = 0; nf < 4; nf++) {
                const int gg = warp_n + nf * 8 + c2i;
                E[h0r * 128 + gg    ] = (h0r == gg    ) ? NEG_INF : acc[mf][nf][0];
                E[h0r * 128 + gg + 1] = (h0r == gg + 1) ? NEG_INF : acc[mf][nf][1];
                E[h1r * 128 + gg    ] = (h1r == gg    ) ? NEG_INF : acc[mf][nf][2];
                E[h1r * 128 + gg + 1] = (h1r == gg + 1) ? NEG_INF : acc[mf][nf][3];
            }
        }
    }
    __syncthreads();

    for (int r = wid; r < 128; r += 8) {
        float* row = E + r * 128;
        float v0 = row[lane], v1 = row[lane + 32], v2 = row[lane + 64], v3 = row[lane + 96];
        float mx = fmaxf(fmaxf(v0, v1), fmaxf(v2, v3));
#pragma unroll
        for (int o = 16; o > 0; o >>= 1) mx = fmaxf(mx, __shfl_xor_sync(0xffffffffu, mx, o));
        v0 = __expf(v0 - mx); v1 = __expf(v1 - mx);
        v2 = __expf(v2 - mx); v3 = __expf(v3 - mx);
        float s = v0 + v1 + v2 + v3;
#pragma unroll
        for (int o = 16; o > 0; o >>= 1) s += __shfl_xor_sync(0xffffffffu, s, o);
        const float inv = 1.f / s;
        Ahi[r * 136 + lane     ] = __float2half_rn(v0 * inv);
        Ahi[r * 136 + lane + 32] = __float2half_rn(v1 * inv);
        Ahi[r * 136 + lane + 64] = __float2half_rn(v2 * inv);
        Ahi[r * 136 + lane + 96] = __float2half_rn(v3 * inv);
    }
    __syncthreads();

    // ---- Phase 2: 32-col chunks, 4-stage single-sync V pipeline ----
    auto loadV = [&](int s, int ci) {
        const uint32_t stg = sb + s * VST_B;
        const int c0 = ci * 32;
#pragma unroll
        for (int t = 0; t < 2; t++) {
            const int idx = tid + t * 256;
            const int row = idx >> 2, seg = idx & 3;
            const uint32_t doff = (uint32_t)(row * 80 + seg * 16);
            cp16(stg + doff, v16 + (size_t)row * Cn + c0 + seg * 8);
        }
        asm volatile("cp.async.commit_group;" ::: "memory");
    };

    loadV(0, 0);
    loadV(1, 1);
    loadV(2, 2);

    const int h0 = wid * 16;
    uint32_t Ah[8][4];
    {
        const uint32_t abase = sb + A_OFF +
            (uint32_t)(((h0 + (lane & 15)) * 136 + (lane >> 4) * 8) * 2);
#pragma unroll
        for (int ks = 0; ks < 8; ks++)
            ldsm_x4(Ah[ks], abase + ks * 32);
    }

    const float gam = gamma_p[0];
    const uint32_t v_lane = (uint32_t)(((lane & 7) + ((lane >> 3) & 1) * 8) * 80 +
                                       (lane >> 4) * 16);

    for (int ci = 0; ci < 16; ci++) {
        if (ci <= 13)      asm volatile("cp.async.wait_group 2;" ::: "memory");
        else if (ci == 14) asm volatile("cp.async.wait_group 1;" ::: "memory");
        else               asm volatile("cp.async.wait_group 0;" ::: "memory");
        __syncthreads();
        if (ci + 3 < 16) loadV((ci + 3) & 3, ci + 3);

        const uint32_t vs = sb + (ci & 3) * VST_B;

        float acc2[4][4];
#pragma unroll
        for (int j = 0; j < 4; j++)
#pragma unroll
            for (int q = 0; q < 4; q++) acc2[j][q] = 0.f;

#pragma unroll
        for (int ks = 0; ks < 8; ks++) {
            const uint32_t vrow = vs + (uint32_t)(ks * 16 * 80) + v_lane;
            uint32_t bh0[4], bh1[4];
            ldsm_x4_t(bh0, vrow);
            ldsm_x4_t(bh1, vrow + 32);
            mma_f16(acc2[0], Ah[ks], bh0);
            mma_f16(acc2[1], Ah[ks], bh0 + 2);
            mma_f16(acc2[2], Ah[ks], bh1);
            mma_f16(acc2[3], Ah[ks], bh1 + 2);
        }

        const int hr = h0 + (lane >> 2);
#pragma unroll
        for (int j = 0; j < 4; j++) {
            const int c = ci * 32 + j * 8 + (lane & 3) * 2;
            const size_t o0 = ((size_t)(b * Hn + hr)     * Wn + w) * Cn + c;
            const size_t o1 = ((size_t)(b * Hn + hr + 8) * Wn + w) * Cn + c;
            float2 x0 = *(const float2*)(x + o0);
            float2 x1 = *(const float2*)(x + o1);
            float2 r0, r1;
            r0.x = fmaf(gam, acc2[j][0], x0.x);
            r0.y = fmaf(gam, acc2[j][1], x0.y);
            r1.x = fmaf(gam, acc2[j][2], x1.x);
            r1.y = fmaf(gam, acc2[j][3], x1.y);
            *(float2*)(out + o0) = r0;
            *(float2*)(out + o1) = r1;
        }
    }
}

// ---------------------------------------------------------------------------
extern "C" void kernel_launch(void* const* d_in, const int* in_sizes, int n_in,
                              void* d_out, int out_size)
{
    const float* x  = (const float*)d_in[0];
    const float* Wq = (const float*)d_in[1];
    const float* Wk = (const float*)d_in[2];
    const float* Wv = (const float*)d_in[3];
    const float* gm = (const float*)d_in[4];
    float* out = (float*)d_out;

    wm_mma<<<dim3(8, 8), 256>>>(Wq, Wk);
    split_xt<<<MTOT + 512, 128>>>(x, Wv);   // tail blocks convert Wv

    cudaFuncSetAttribute(qkv_fused, cudaFuncAttributeMaxDynamicSharedMemorySize, 2 * STG_B);
    qkv_fused<<<8192, 256, 2 * STG_B>>>();

    cudaFuncSetAttribute(cc_attn, cudaFuncAttributeMaxDynamicSharedMemorySize, CC_SMEM);
    cc_attn<<<NCOL, 256, CC_SMEM>>>(x, gm, out);
}